// round 2
// baseline (speedup 1.0000x reference)
#include <cuda_runtime.h>
#include <cstdint>

// Problem constants (fixed shapes for this problem)
#define MAXE 400000
#define MAXN 25000

// Scratch (device globals; allocation-free per harness rules).
// g_feat: feat[E,384] for inv block; later reused as cat2[E,320] for merge block.
// g_h1:   h1[E,384] pre-activation; later reused as h2[E,128].
__device__ float g_feat[(size_t)MAXE * 384];
__device__ float g_h1[(size_t)MAXE * 384];
__device__ unsigned char g_mask[MAXE];
__device__ int g_last;

// ---------------------------------------------------------------------------
// init: zero node output region, reset last index
__global__ __launch_bounds__(256) void k_init(float* __restrict__ node, int n)
{
    int i = blockIdx.x * 256 + threadIdx.x;
    if (i == 0) g_last = -1;
    if (i < n) node[i] = 0.f;
}

// ---------------------------------------------------------------------------
// mask: raw mask + atomicMax for the "drop last true index" semantics
__global__ __launch_bounds__(256) void k_mask(const int* __restrict__ src,
                                              const int* __restrict__ dst, int E)
{
    int e = blockIdx.x * 256 + threadIdx.x;
    if (e >= E) return;
    bool m = false;
    if (e + 1 < E)
        m = (src[e] == src[e + 1]) && (src[e] != dst[e]) && (src[e + 1] != dst[e + 1]);
    g_mask[e] = m ? 1 : 0;
    if (m) atomicMax(&g_last, e);
}

// ---------------------------------------------------------------------------
// feat: build segments 0..4 of feat[E,384] (seg5 = angle output, written by k_angle)
// one warp per edge; 80 float4 per row for segs 0..4 (320 floats)
__global__ __launch_bounds__(256) void k_feat(const float* __restrict__ atom,
                                              const float* __restrict__ el,
                                              const int* __restrict__ src,
                                              const int* __restrict__ dst, int E)
{
    int e = (blockIdx.x * 256 + threadIdx.x) >> 5;
    int lane = threadIdx.x & 31;
    if (e >= E) return;
    bool m = (g_mask[e] != 0) && (e != g_last);
    float4* out = (float4*)(g_feat + (size_t)e * 384);
    if (!m) {
        float4 z = make_float4(0.f, 0.f, 0.f, 0.f);
        out[lane] = z;
        out[lane + 32] = z;
        if (lane < 16) out[lane + 64] = z;
        return;
    }
    int s = src[e], d = dst[e], d2 = dst[e + 1];
    const float4* p0 = (const float4*)(atom + (size_t)s * 64);
    const float4* p1 = (const float4*)(atom + (size_t)d * 64);
    const float4* p2 = (const float4*)(el + (size_t)e * 64);
    const float4* p3 = (const float4*)(atom + (size_t)d2 * 64);
    const float4* p4 = (const float4*)(el + (size_t)(e + 1) * 64);
    out[lane]      = (lane < 16) ? p0[lane] : p1[lane - 16];
    out[lane + 32] = (lane < 16) ? p2[lane] : p3[lane - 16];
    if (lane < 16) out[lane + 64] = p4[lane];
}

// ---------------------------------------------------------------------------
// angle block: cos -> Linear(1,64) -> LN -> SiLU -> Linear(64,64), write feat seg5
// one thread per edge; w2 in smem (broadcast float4 reads)
__global__ __launch_bounds__(128) void k_angle(const float* __restrict__ ev,
                                               const float* __restrict__ w1,
                                               const float* __restrict__ b1,
                                               const float* __restrict__ g,
                                               const float* __restrict__ bn,
                                               const float* __restrict__ w2,
                                               const float* __restrict__ b2, int E)
{
    __shared__ float sw2[64 * 64];
    __shared__ float sv[5 * 64];  // w1, b1, g, bn, b2
    for (int i = threadIdx.x; i < 64 * 64; i += 128) sw2[i] = w2[i];
    if (threadIdx.x < 64) {
        int i = threadIdx.x;
        sv[i] = w1[i]; sv[64 + i] = b1[i]; sv[128 + i] = g[i];
        sv[192 + i] = bn[i]; sv[256 + i] = b2[i];
    }
    __syncthreads();
    int e = blockIdx.x * 128 + threadIdx.x;
    if (e >= E) return;
    int last = g_last;
    bool m0 = (g_mask[e] != 0) && (e != last);
    float* out = g_feat + (size_t)e * 384 + 320;
    if (!m0) {
        float4 z = make_float4(0.f, 0.f, 0.f, 0.f);
        #pragma unroll
        for (int n = 0; n < 16; n++) ((float4*)out)[n] = z;
        return;
    }
    float c = 0.f;
    if (e + 1 < E && (g_mask[e + 1] != 0) && (e + 1 != last)) {
        float ax = ev[3 * e],       ay = ev[3 * e + 1],       az = ev[3 * e + 2];
        float bx = ev[3 * (e + 1)], by = ev[3 * (e + 1) + 1], bz = ev[3 * (e + 1) + 2];
        float ra = rsqrtf(ax * ax + ay * ay + az * az);
        float rb = rsqrtf(bx * bx + by * by + bz * bz);
        c = (ax * bx + ay * by + az * bz) * ra * rb;
    }
    float x[64];
    float s = 0.f;
    #pragma unroll
    for (int j = 0; j < 64; j++) { x[j] = fmaf(c, sv[j], sv[64 + j]); s += x[j]; }
    float mean = s * (1.f / 64.f);
    float var = 0.f;
    #pragma unroll
    for (int j = 0; j < 64; j++) { float d = x[j] - mean; var = fmaf(d, d, var); }
    var *= (1.f / 64.f);
    float rs = rsqrtf(var + 1e-6f);
    #pragma unroll
    for (int j = 0; j < 64; j++) {
        float t = (x[j] - mean) * rs * sv[128 + j] + sv[192 + j];
        x[j] = t / (1.f + expf(-t));
    }
    #pragma unroll 4
    for (int n = 0; n < 64; n++) {
        float acc = sv[256 + n];
        const float4* wr = (const float4*)(sw2 + n * 64);
        #pragma unroll
        for (int j4 = 0; j4 < 16; j4++) {
            float4 w4 = wr[j4];
            acc = fmaf(x[4 * j4], w4.x, acc);
            acc = fmaf(x[4 * j4 + 1], w4.y, acc);
            acc = fmaf(x[4 * j4 + 2], w4.z, acc);
            acc = fmaf(x[4 * j4 + 3], w4.w, acc);
        }
        out[n] = acc;
    }
}

// ---------------------------------------------------------------------------
// cat2: [node[src] | node[dst] | el] -> g_feat reused as [E,320]
__global__ __launch_bounds__(256) void k_cat2(const float* __restrict__ node,
                                              const float* __restrict__ el,
                                              const int* __restrict__ src,
                                              const int* __restrict__ dst, int E)
{
    int e = (blockIdx.x * 256 + threadIdx.x) >> 5;
    int lane = threadIdx.x & 31;
    if (e >= E) return;
    int s = src[e], d = dst[e];
    float4* out = (float4*)(g_feat + (size_t)e * 320);
    out[lane]      = ((const float4*)(node + (size_t)s * 128))[lane];
    out[lane + 32] = ((const float4*)(node + (size_t)d * 128))[lane];
    if (lane < 16) out[lane + 64] = ((const float4*)(el + (size_t)e * 64))[lane];
}

// ---------------------------------------------------------------------------
// SGEMM: C[M,N] = A[M,K] @ W[N,K]^T + bias   (A row-major, W = torch Linear weight)
// block tile 128x128, BK=16, 256 threads, 8x8 microtile.
// ATOMIC=1: scatter-add rows into node[dstIdx[row]] (segment_sum fused epilogue)
#define BM 128
#define BN 128
#define BKK 16

template <int ATOMIC>
__global__ __launch_bounds__(256) void sgemm_nt(const float* __restrict__ A,
                                                const float* __restrict__ W,
                                                const float* __restrict__ bias,
                                                float* __restrict__ C, int N, int K,
                                                const int* __restrict__ dstIdx)
{
    __shared__ float As[BKK][BM];
    __shared__ float Ws[BKK][BN];
    int tid = threadIdx.x;
    int tx = tid & 15, ty = tid >> 4;
    const float* Ag = A + (size_t)blockIdx.x * BM * K;
    const float* Wg = W + (size_t)blockIdx.y * BN * K;
    float acc[8][8] = {};
    int lr = tid >> 2;         // 0..63
    int lc = (tid & 3) * 4;    // 0,4,8,12

    for (int k0 = 0; k0 < K; k0 += BKK) {
        #pragma unroll
        for (int h = 0; h < 2; h++) {
            int r = lr + h * 64;
            float4 av = *(const float4*)(Ag + (size_t)r * K + k0 + lc);
            As[lc + 0][r] = av.x; As[lc + 1][r] = av.y;
            As[lc + 2][r] = av.z; As[lc + 3][r] = av.w;
            float4 wv = *(const float4*)(Wg + (size_t)r * K + k0 + lc);
            Ws[lc + 0][r] = wv.x; Ws[lc + 1][r] = wv.y;
            Ws[lc + 2][r] = wv.z; Ws[lc + 3][r] = wv.w;
        }
        __syncthreads();
        #pragma unroll
        for (int kk = 0; kk < BKK; kk++) {
            float a[8], w[8];
            *(float4*)&a[0] = *(const float4*)&As[kk][ty * 8];
            *(float4*)&a[4] = *(const float4*)&As[kk][ty * 8 + 4];
            *(float4*)&w[0] = *(const float4*)&Ws[kk][tx * 8];
            *(float4*)&w[4] = *(const float4*)&Ws[kk][tx * 8 + 4];
            #pragma unroll
            for (int i = 0; i < 8; i++)
                #pragma unroll
                for (int j = 0; j < 8; j++)
                    acc[i][j] = fmaf(a[i], w[j], acc[i][j]);
        }
        __syncthreads();
    }

    int m0 = blockIdx.x * BM + ty * 8;
    int n0 = blockIdx.y * BN + tx * 8;
    if (ATOMIC) {
        #pragma unroll
        for (int i = 0; i < 8; i++) {
            int d = dstIdx[m0 + i];
            float* cr = C + (size_t)d * N + n0;
            #pragma unroll
            for (int j = 0; j < 8; j++)
                atomicAdd(cr + j, acc[i][j] + bias[n0 + j]);
        }
    } else {
        #pragma unroll
        for (int i = 0; i < 8; i++) {
            float* cr = C + (size_t)(m0 + i) * N + n0;
            #pragma unroll
            for (int j = 0; j < 8; j++)
                cr[j] = acc[i][j] + bias[n0 + j];
        }
    }
}

// ---------------------------------------------------------------------------
// LayerNorm + SiLU in place, one warp per row, D % 32 == 0
template <int D>
__global__ __launch_bounds__(256) void ln_silu(float* __restrict__ X,
                                               const float* __restrict__ g,
                                               const float* __restrict__ b, int M)
{
    int row = blockIdx.x * 8 + (threadIdx.x >> 5);
    int lane = threadIdx.x & 31;
    if (row >= M) return;
    float* x = X + (size_t)row * D;
    constexpr int Cc = D / 32;
    float v[Cc];
    float s = 0.f, s2 = 0.f;
    #pragma unroll
    for (int c = 0; c < Cc; c++) {
        v[c] = x[c * 32 + lane];
        s += v[c];
        s2 = fmaf(v[c], v[c], s2);
    }
    #pragma unroll
    for (int o = 16; o; o >>= 1) {
        s += __shfl_xor_sync(0xffffffffu, s, o);
        s2 += __shfl_xor_sync(0xffffffffu, s2, o);
    }
    float mean = s * (1.f / D);
    float var = s2 * (1.f / D) - mean * mean;
    float rs = rsqrtf(var + 1e-6f);
    #pragma unroll
    for (int c = 0; c < Cc; c++) {
        float t = (v[c] - mean) * rs * g[c * 32 + lane] + b[c * 32 + lane];
        x[c * 32 + lane] = t / (1.f + expf(-t));
    }
}

// ---------------------------------------------------------------------------
extern "C" void kernel_launch(void* const* d_in, const int* in_sizes, int n_in,
                              void* d_out, int out_size)
{
    const float* atom = (const float*)d_in[0];
    const float* el   = (const float*)d_in[1];
    const float* ev   = (const float*)d_in[2];
    const int* eidx   = (const int*)d_in[3];
    const float* aw1 = (const float*)d_in[4];
    const float* ab1 = (const float*)d_in[5];
    const float* ag  = (const float*)d_in[6];
    const float* abn = (const float*)d_in[7];
    const float* aw2 = (const float*)d_in[8];
    const float* ab2 = (const float*)d_in[9];
    const float* iw1 = (const float*)d_in[10];
    const float* ib1 = (const float*)d_in[11];
    const float* ig  = (const float*)d_in[12];
    const float* ibn = (const float*)d_in[13];
    const float* iw2 = (const float*)d_in[14];
    const float* ib2 = (const float*)d_in[15];
    const float* mw1 = (const float*)d_in[16];
    const float* mb1 = (const float*)d_in[17];
    const float* mg  = (const float*)d_in[18];
    const float* mbn = (const float*)d_in[19];
    const float* mw2 = (const float*)d_in[20];
    const float* mb2 = (const float*)d_in[21];

    int Na = in_sizes[0] / 64;   // 25000
    int E  = in_sizes[2] / 3;    // 400000
    const int* src = eidx;
    const int* dst = eidx + E;
    float* node = (float*)d_out;
    float* edge = node + (size_t)Na * 128;

    float *feat, *h1;
    cudaGetSymbolAddress((void**)&feat, g_feat);
    cudaGetSymbolAddress((void**)&h1, g_h1);

    // 1) zero node accumulator + reset last
    k_init<<<(Na * 128 + 255) / 256, 256>>>(node, Na * 128);
    // 2) mask + last index
    k_mask<<<(E + 255) / 256, 256>>>(src, dst, E);
    // 3) feat segments 0..4 (warp/edge)
    k_feat<<<(E * 32 + 255) / 256, 256>>>(atom, el, src, dst, E);
    // 4) angle block -> feat segment 5
    k_angle<<<(E + 127) / 128, 128>>>(ev, aw1, ab1, ag, abn, aw2, ab2, E);
    // 5) h1 = feat @ iw1^T + ib1
    sgemm_nt<0><<<dim3(E / 128, 3), 256>>>(feat, iw1, ib1, h1, 384, 384, nullptr);
    // 6) h1 = silu(ln(h1))
    ln_silu<384><<<(E + 7) / 8, 256>>>(h1, ig, ibn, E);
    // 7) node += scatter(h1 @ iw2^T + ib2) over dst
    sgemm_nt<1><<<dim3(E / 128, 1), 256>>>(h1, iw2, ib2, node, 128, 384, dst);
    // 8) cat2 = [node[src] | node[dst] | el] (reuses g_feat)
    k_cat2<<<(E * 32 + 255) / 256, 256>>>(node, el, src, dst, E);
    // 9) h2 = cat2 @ mw1^T + mb1 (reuses g_h1)
    sgemm_nt<0><<<dim3(E / 128, 1), 256>>>(feat, mw1, mb1, h1, 128, 320, nullptr);
    // 10) h2 = silu(ln(h2))
    ln_silu<128><<<(E + 7) / 8, 256>>>(h1, mg, mbn, E);
    // 11) edge = h2 @ mw2^T + mb2
    sgemm_nt<0><<<dim3(E / 128, 1), 256>>>(h1, mw2, mb2, edge, 128, 128, nullptr);
}

// round 8
// speedup vs baseline: 2.0028x; 2.0028x over previous
#include <cuda_runtime.h>
#include <cuda_bf16.h>
#include <cstdint>

#define MAXE 400000
#define MAXN 25000

// ---------------------------------------------------------------------------
// Device scratch. A2/B2 hold hi|lo concatenated bf16 rows (width 2K).
__device__ __nv_bfloat16 g_A2[(size_t)MAXE * 768];
__device__ __nv_bfloat16 g_B2[(size_t)MAXE * 768];
__device__ float g_h1[(size_t)MAXE * 384];
__device__ __nv_bfloat16 g_W2[507904];
__device__ unsigned char g_mask[MAXE];
__device__ int g_last;

// weight pool offsets (bf16 elements), rows are [hi(K) | lo(K)]
#define OFF_IW1 0         // 384 x 768
#define OFF_IW2 294912    // 128 x 768
#define OFF_MW1 393216    // 128 x 640
#define OFF_MW2 475136    // 128 x 256

// ---------------------------------------------------------------------------
static __device__ __forceinline__ uint32_t smem_u32(const void* p) {
    uint32_t a;
    asm("{ .reg .u64 t; cvta.to.shared.u64 t, %1; cvt.u32.u64 %0, t; }" : "=r"(a) : "l"(p));
    return a;
}
static __device__ __forceinline__ void cp_async16(uint32_t s, const void* g) {
    asm volatile("cp.async.cg.shared.global [%0], [%1], 16;" :: "r"(s), "l"(g));
}
static __device__ __forceinline__ void cp_commit() {
    asm volatile("cp.async.commit_group;" ::: "memory");
}
template <int N>
static __device__ __forceinline__ void cp_wait() {
    asm volatile("cp.async.wait_group %0;" :: "n"(N) : "memory");
}
static __device__ __forceinline__ void ldsm4(uint32_t* r, uint32_t a) {
    asm volatile("ldmatrix.sync.aligned.m8n8.x4.shared.b16 {%0,%1,%2,%3}, [%4];"
                 : "=r"(r[0]), "=r"(r[1]), "=r"(r[2]), "=r"(r[3]) : "r"(a));
}
static __device__ __forceinline__ void mma16816(float* d, const uint32_t* a, const uint32_t* b) {
    asm volatile(
        "mma.sync.aligned.m16n8k16.row.col.f32.bf16.bf16.f32 "
        "{%0,%1,%2,%3}, {%4,%5,%6,%7}, {%8,%9}, {%0,%1,%2,%3};"
        : "+f"(d[0]), "+f"(d[1]), "+f"(d[2]), "+f"(d[3])
        : "r"(a[0]), "r"(a[1]), "r"(a[2]), "r"(a[3]), "r"(b[0]), "r"(b[1]));
}

static __device__ __forceinline__ uint32_t pack2(__nv_bfloat16 a, __nv_bfloat16 b) {
    __nv_bfloat162 t = __halves2bfloat162(a, b);
    return *reinterpret_cast<uint32_t*>(&t);
}
static __device__ __forceinline__ void split1(float x, __nv_bfloat16& h, __nv_bfloat16& l) {
    h = __float2bfloat16(x);
    l = __float2bfloat16(x - __bfloat162float(h));
}
static __device__ __forceinline__ void split_store(uint2* oh, uint2* ol, int slot, float4 v) {
    __nv_bfloat16 h0, h1, h2, h3, l0, l1, l2, l3;
    split1(v.x, h0, l0); split1(v.y, h1, l1);
    split1(v.z, h2, l2); split1(v.w, h3, l3);
    uint2 uh, ul;
    uh.x = pack2(h0, h1); uh.y = pack2(h2, h3);
    ul.x = pack2(l0, l1); ul.y = pack2(l2, l3);
    oh[slot] = uh; ol[slot] = ul;
}

// ---------------------------------------------------------------------------
__global__ __launch_bounds__(256) void k_init(float* __restrict__ node, int n)
{
    int i = blockIdx.x * 256 + threadIdx.x;
    if (i == 0) g_last = -1;
    if (i < n) node[i] = 0.f;
}

__global__ __launch_bounds__(256) void k_mask(const int* __restrict__ src,
                                              const int* __restrict__ dst, int E)
{
    int e = blockIdx.x * 256 + threadIdx.x;
    if (e >= E) return;
    bool m = false;
    if (e + 1 < E)
        m = (src[e] == src[e + 1]) && (src[e] != dst[e]) && (src[e + 1] != dst[e + 1]);
    g_mask[e] = m ? 1 : 0;
    if (m) atomicMax(&g_last, e);
}

// split fp32 weight [N,K] -> bf16 [N, 2K] rows [hi | lo]
__global__ __launch_bounds__(256) void k_split(const float* __restrict__ w,
                                               __nv_bfloat16* __restrict__ out,
                                               int Nr, int K)
{
    int i = blockIdx.x * 256 + threadIdx.x;
    if (i >= Nr * K) return;
    int n = i / K, k = i - n * K;
    __nv_bfloat16 h, l;
    split1(w[i], h, l);
    out[(size_t)n * 2 * K + k] = h;
    out[(size_t)n * 2 * K + K + k] = l;
}

// feat -> A2 [E,768]: hi cols 0..319, lo cols 384..703 (angle fills 320..383 / 704..767)
__global__ __launch_bounds__(256) void k_feat(const float* __restrict__ atom,
                                              const float* __restrict__ el,
                                              const int* __restrict__ src,
                                              const int* __restrict__ dst, int E)
{
    int e = (blockIdx.x * 256 + threadIdx.x) >> 5;
    int lane = threadIdx.x & 31;
    if (e >= E) return;
    bool m = (g_mask[e] != 0) && (e != g_last);
    uint2* oh = (uint2*)(g_A2 + (size_t)e * 768);
    uint2* ol = (uint2*)(g_A2 + (size_t)e * 768 + 384);
    if (!m) {
        uint2 z = make_uint2(0u, 0u);
        oh[lane] = z; ol[lane] = z;
        oh[lane + 32] = z; ol[lane + 32] = z;
        if (lane < 16) { oh[lane + 64] = z; ol[lane + 64] = z; }
        return;
    }
    int s = src[e], d = dst[e], d2 = dst[e + 1];
    const float4* p0 = (const float4*)(atom + (size_t)s * 64);
    const float4* p1 = (const float4*)(atom + (size_t)d * 64);
    const float4* p2 = (const float4*)(el + (size_t)e * 64);
    const float4* p3 = (const float4*)(atom + (size_t)d2 * 64);
    const float4* p4 = (const float4*)(el + (size_t)(e + 1) * 64);
    float4 v0 = (lane < 16) ? p0[lane] : p1[lane - 16];
    float4 v1 = (lane < 16) ? p2[lane] : p3[lane - 16];
    split_store(oh, ol, lane, v0);
    split_store(oh, ol, lane + 32, v1);
    if (lane < 16) split_store(oh, ol, lane + 64, p4[lane]);
}

// angle block -> A2 hi cols 320..383, lo cols 704..767
__global__ __launch_bounds__(128) void k_angle(const float* __restrict__ ev,
                                               const float* __restrict__ w1,
                                               const float* __restrict__ b1,
                                               const float* __restrict__ g,
                                               const float* __restrict__ bn,
                                               const float* __restrict__ w2,
                                               const float* __restrict__ b2, int E)
{
    __shared__ float sw2[64 * 64];
    __shared__ float sv[5 * 64];
    for (int i = threadIdx.x; i < 64 * 64; i += 128) sw2[i] = w2[i];
    if (threadIdx.x < 64) {
        int i = threadIdx.x;
        sv[i] = w1[i]; sv[64 + i] = b1[i]; sv[128 + i] = g[i];
        sv[192 + i] = bn[i]; sv[256 + i] = b2[i];
    }
    __syncthreads();
    int e = blockIdx.x * 128 + threadIdx.x;
    if (e >= E) return;
    int last = g_last;
    bool m0 = (g_mask[e] != 0) && (e != last);
    uint2* oh = (uint2*)(g_A2 + (size_t)e * 768 + 320);
    uint2* ol = (uint2*)(g_A2 + (size_t)e * 768 + 704);
    if (!m0) {
        uint2 z = make_uint2(0u, 0u);
        #pragma unroll
        for (int n = 0; n < 16; n++) { oh[n] = z; ol[n] = z; }
        return;
    }
    float c = 0.f;
    if (e + 1 < E && (g_mask[e + 1] != 0) && (e + 1 != last)) {
        float ax = ev[3 * e],       ay = ev[3 * e + 1],       az = ev[3 * e + 2];
        float bx = ev[3 * (e + 1)], by = ev[3 * (e + 1) + 1], bz = ev[3 * (e + 1) + 2];
        float ra = rsqrtf(ax * ax + ay * ay + az * az);
        float rb = rsqrtf(bx * bx + by * by + bz * bz);
        c = (ax * bx + ay * by + az * bz) * ra * rb;
    }
    float x[64];
    float s = 0.f;
    #pragma unroll
    for (int j = 0; j < 64; j++) { x[j] = fmaf(c, sv[j], sv[64 + j]); s += x[j]; }
    float mean = s * (1.f / 64.f);
    float var = 0.f;
    #pragma unroll
    for (int j = 0; j < 64; j++) { float d = x[j] - mean; var = fmaf(d, d, var); }
    var *= (1.f / 64.f);
    float rs = rsqrtf(var + 1e-6f);
    #pragma unroll
    for (int j = 0; j < 64; j++) {
        float t = (x[j] - mean) * rs * sv[128 + j] + sv[192 + j];
        x[j] = t / (1.f + expf(-t));
    }
    float y[64];
    #pragma unroll 4
    for (int n = 0; n < 64; n++) {
        float acc = sv[256 + n];
        const float4* wr = (const float4*)(sw2 + n * 64);
        #pragma unroll
        for (int j4 = 0; j4 < 16; j4++) {
            float4 w4 = wr[j4];
            acc = fmaf(x[4 * j4], w4.x, acc);
            acc = fmaf(x[4 * j4 + 1], w4.y, acc);
            acc = fmaf(x[4 * j4 + 2], w4.z, acc);
            acc = fmaf(x[4 * j4 + 3], w4.w, acc);
        }
        y[n] = acc;
    }
    #pragma unroll
    for (int n = 0; n < 16; n++) {
        float4 v = make_float4(y[4 * n], y[4 * n + 1], y[4 * n + 2], y[4 * n + 3]);
        split_store(oh, ol, n, v);
    }
}

// cat2 -> A2 reused as [E,640]: hi 0..319, lo 320..639
__global__ __launch_bounds__(256) void k_cat2(const float* __restrict__ node,
                                              const float* __restrict__ el,
                                              const int* __restrict__ src,
                                              const int* __restrict__ dst, int E)
{
    int e = (blockIdx.x * 256 + threadIdx.x) >> 5;
    int lane = threadIdx.x & 31;
    if (e >= E) return;
    int s = src[e], d = dst[e];
    uint2* oh = (uint2*)(g_A2 + (size_t)e * 640);
    uint2* ol = (uint2*)(g_A2 + (size_t)e * 640 + 320);
    split_store(oh, ol, lane,      ((const float4*)(node + (size_t)s * 128))[lane]);
    split_store(oh, ol, lane + 32, ((const float4*)(node + (size_t)d * 128))[lane]);
    if (lane < 16)
        split_store(oh, ol, lane + 64, ((const float4*)(el + (size_t)e * 64))[lane]);
}

// LayerNorm + SiLU, fp32 in -> hi|lo bf16 rows of width 2D
template <int D>
__global__ __launch_bounds__(256) void ln_silu_split(const float* __restrict__ X,
                                                     const float* __restrict__ g,
                                                     const float* __restrict__ b,
                                                     __nv_bfloat16* __restrict__ O, int M)
{
    int row = blockIdx.x * 8 + (threadIdx.x >> 5);
    int lane = threadIdx.x & 31;
    if (row >= M) return;
    const float* x = X + (size_t)row * D;
    constexpr int Cc = D / 32;
    float v[Cc];
    float s = 0.f, s2 = 0.f;
    #pragma unroll
    for (int c = 0; c < Cc; c++) {
        v[c] = x[c * 32 + lane];
        s += v[c];
        s2 = fmaf(v[c], v[c], s2);
    }
    #pragma unroll
    for (int o = 16; o; o >>= 1) {
        s += __shfl_xor_sync(0xffffffffu, s, o);
        s2 += __shfl_xor_sync(0xffffffffu, s2, o);
    }
    float mean = s * (1.f / D);
    float var = s2 * (1.f / D) - mean * mean;
    float rs = rsqrtf(var + 1e-6f);
    __nv_bfloat16* hr = O + (size_t)row * 2 * D;
    __nv_bfloat16* lr = hr + D;
    #pragma unroll
    for (int c = 0; c < Cc; c++) {
        float t = (v[c] - mean) * rs * g[c * 32 + lane] + b[c * 32 + lane];
        t = t / (1.f + expf(-t));
        __nv_bfloat16 hh, ll; split1(t, hh, ll);
        hr[c * 32 + lane] = hh;
        lr[c * 32 + lane] = ll;
    }
}

// ---------------------------------------------------------------------------
// bf16x3 mma.sync GEMM: C = (Ah+Al)(Wh+Wl)^T + bias, dropping Al*Wl.
// A stored [M, 2K] rows [Ah|Al]; W stored [N, 2K] rows [Wh|Wl].
// Virtual K = 3K: chunks [0,NCK) -> (Ah,Wh), [NCK,2NCK) -> (Ah,Wl),
// [2NCK,3NCK) -> (Al,Wh).  128x128 block, BK=64, 256 thr (8 warps 4Mx2N).
// ATOMIC=1: scatter-add rows into C[dstIdx[row]].
#define SM_STRIDE 144              // 64 bf16 + 8 pad = 144 bytes per row
#define SM_TILE   (128 * SM_STRIDE)
#define SM_STAGE  (2 * SM_TILE)
#define SMEM_BYTES (2 * SM_STAGE)  // double-buffered A+W

template <int ATOMIC>
__global__ __launch_bounds__(256, 1) void gemm_mma(const __nv_bfloat16* __restrict__ A,
                                                   const __nv_bfloat16* __restrict__ W,
                                                   const float* __restrict__ bias,
                                                   float* __restrict__ C, int Nn, int Kseg,
                                                   const int* __restrict__ dstIdx)
{
    extern __shared__ char smem[];
    const uint32_t sb = smem_u32(smem);
    const int tid = threadIdx.x;
    const int lane = tid & 31, wid = tid >> 5;
    const int warp_m = wid & 3, warp_n = wid >> 2;
    const int n0 = blockIdx.x * 128;
    const int m0 = blockIdx.y * 128;
    const int K2 = 2 * Kseg;
    const int NCK = Kseg >> 6;     // 64-chunks per segment
    const int NC = 3 * NCK;        // virtual chunk count

    float acc[2][8][4] = {};

    // chunk -> (A k-offset, W k-offset) per bf16x3 segment mapping
    auto load_stage = [&](int c, int s) {
        int seg1 = (c >= NCK), seg2 = (c >= 2 * NCK);
        int rem = c - (seg2 ? 2 * NCK : (seg1 ? NCK : 0));
        int a_k0 = (seg2 ? Kseg : 0) + (rem << 6);
        int w_k0 = ((seg1 && !seg2) ? Kseg : 0) + (rem << 6);
        uint32_t sa = sb + s * SM_STAGE;
        uint32_t sw = sa + SM_TILE;
        #pragma unroll
        for (int i = 0; i < 4; i++) {
            int idx = tid + i * 256;
            int r = idx >> 3, c16 = idx & 7;
            cp_async16(sa + r * SM_STRIDE + c16 * 16,
                       A + (size_t)(m0 + r) * K2 + a_k0 + c16 * 8);
            cp_async16(sw + r * SM_STRIDE + c16 * 16,
                       W + (size_t)(n0 + r) * K2 + w_k0 + c16 * 8);
        }
        cp_commit();
    };

    load_stage(0, 0);

    for (int c = 0; c < NC; c++) {
        if (c + 1 < NC) { load_stage(c + 1, (c + 1) & 1); cp_wait<1>(); }
        else            { cp_wait<0>(); }
        __syncthreads();

        uint32_t sa = sb + (c & 1) * SM_STAGE;
        uint32_t sw = sa + SM_TILE;
        int arow = warp_m * 32 + (lane & 15);
        uint32_t a_ko = (uint32_t)((lane >> 4) * 16);
        int nrow = warp_n * 64 + ((lane >> 4) & 1) * 8 + (lane & 7);
        uint32_t b_ko = (uint32_t)(((lane >> 3) & 1) * 16);

        #pragma unroll
        for (int kk = 0; kk < 4; kk++) {
            uint32_t kb = (uint32_t)(kk * 32);
            uint32_t af[2][4];
            ldsm4(af[0], sa + arow * SM_STRIDE + kb + a_ko);
            ldsm4(af[1], sa + (arow + 16) * SM_STRIDE + kb + a_ko);
            uint32_t bf[8][2];
            #pragma unroll
            for (int in4 = 0; in4 < 4; in4++) {
                uint32_t q[4];
                ldsm4(q, sw + (nrow + in4 * 16) * SM_STRIDE + kb + b_ko);
                bf[in4 * 2][0] = q[0]; bf[in4 * 2][1] = q[1];
                bf[in4 * 2 + 1][0] = q[2]; bf[in4 * 2 + 1][1] = q[3];
            }
            #pragma unroll
            for (int im = 0; im < 2; im++)
                #pragma unroll
                for (int jn = 0; jn < 8; jn++)
                    mma16816(acc[im][jn], af[im], bf[jn]);
        }
        __syncthreads();
    }

    // epilogue
    int tq = lane >> 2, tr = lane & 3;
    int rbase = m0 + warp_m * 32 + tq;
    int cb = n0 + warp_n * 64 + tr * 2;
    if (ATOMIC) {
        #pragma unroll
        for (int im = 0; im < 2; im++) {
            int r0 = rbase + im * 16;
            int d0 = dstIdx[r0], d1 = dstIdx[r0 + 8];
            #pragma unroll
            for (int jn = 0; jn < 8; jn++) {
                int col = cb + jn * 8;
                float b0 = bias[col], b1 = bias[col + 1];
                atomicAdd(C + (size_t)d0 * Nn + col,     acc[im][jn][0] + b0);
                atomicAdd(C + (size_t)d0 * Nn + col + 1, acc[im][jn][1] + b1);
                atomicAdd(C + (size_t)d1 * Nn + col,     acc[im][jn][2] + b0);
                atomicAdd(C + (size_t)d1 * Nn + col + 1, acc[im][jn][3] + b1);
            }
        }
    } else {
        #pragma unroll
        for (int im = 0; im < 2; im++) {
            int r0 = rbase + im * 16;
            #pragma unroll
            for (int jn = 0; jn < 8; jn++) {
                int col = cb + jn * 8;
                float b0 = bias[col], b1 = bias[col + 1];
                float2 v0 = make_float2(acc[im][jn][0] + b0, acc[im][jn][1] + b1);
                float2 v1 = make_float2(acc[im][jn][2] + b0, acc[im][jn][3] + b1);
                *(float2*)(C + (size_t)r0 * Nn + col) = v0;
                *(float2*)(C + (size_t)(r0 + 8) * Nn + col) = v1;
            }
        }
    }
}

// ---------------------------------------------------------------------------
extern "C" void kernel_launch(void* const* d_in, const int* in_sizes, int n_in,
                              void* d_out, int out_size)
{
    const float* atom = (const float*)d_in[0];
    const float* el   = (const float*)d_in[1];
    const float* ev   = (const float*)d_in[2];
    const int* eidx   = (const int*)d_in[3];
    const float* aw1 = (const float*)d_in[4];
    const float* ab1 = (const float*)d_in[5];
    const float* ag  = (const float*)d_in[6];
    const float* abn = (const float*)d_in[7];
    const float* aw2 = (const float*)d_in[8];
    const float* ab2 = (const float*)d_in[9];
    const float* iw1 = (const float*)d_in[10];
    const float* ib1 = (const float*)d_in[11];
    const float* ig  = (const float*)d_in[12];
    const float* ibn = (const float*)d_in[13];
    const float* iw2 = (const float*)d_in[14];
    const float* ib2 = (const float*)d_in[15];
    const float* mw1 = (const float*)d_in[16];
    const float* mb1 = (const float*)d_in[17];
    const float* mg  = (const float*)d_in[18];
    const float* mbn = (const float*)d_in[19];
    const float* mw2 = (const float*)d_in[20];
    const float* mb2 = (const float*)d_in[21];

    int Na = in_sizes[0] / 64;   // 25000
    int E  = in_sizes[2] / 3;    // 400000
    const int* src = eidx;
    const int* dst = eidx + E;
    float* node = (float*)d_out;
    float* edge = node + (size_t)Na * 128;

    __nv_bfloat16 *A2, *B2, *W2;
    float* h1;
    cudaGetSymbolAddress((void**)&A2, g_A2);
    cudaGetSymbolAddress((void**)&B2, g_B2);
    cudaGetSymbolAddress((void**)&W2, g_W2);
    cudaGetSymbolAddress((void**)&h1, g_h1);

    cudaFuncSetAttribute(gemm_mma<0>, cudaFuncAttributeMaxDynamicSharedMemorySize, SMEM_BYTES);
    cudaFuncSetAttribute(gemm_mma<1>, cudaFuncAttributeMaxDynamicSharedMemorySize, SMEM_BYTES);

    int MT = E / 128;  // 3125

    // prep
    k_init<<<(Na * 128 + 255) / 256, 256>>>(node, Na * 128);
    k_mask<<<(E + 255) / 256, 256>>>(src, dst, E);
    k_split<<<(384 * 384 + 255) / 256, 256>>>(iw1, W2 + OFF_IW1, 384, 384);
    k_split<<<(128 * 384 + 255) / 256, 256>>>(iw2, W2 + OFF_IW2, 128, 384);
    k_split<<<(128 * 320 + 255) / 256, 256>>>(mw1, W2 + OFF_MW1, 128, 320);
    k_split<<<(128 * 128 + 255) / 256, 256>>>(mw2, W2 + OFF_MW2, 128, 128);

    // inv block
    k_feat<<<(E * 32 + 255) / 256, 256>>>(atom, el, src, dst, E);
    k_angle<<<(E + 127) / 128, 128>>>(ev, aw1, ab1, ag, abn, aw2, ab2, E);
    gemm_mma<0><<<dim3(3, MT), 256, SMEM_BYTES>>>(A2, W2 + OFF_IW1, ib1, h1, 384, 384, nullptr);
    ln_silu_split<384><<<(E + 7) / 8, 256>>>(h1, ig, ibn, B2, E);
    gemm_mma<1><<<dim3(1, MT), 256, SMEM_BYTES>>>(B2, W2 + OFF_IW2, ib2, node, 128, 384, dst);
    // merge block
    k_cat2<<<(E * 32 + 255) / 256, 256>>>(node, el, src, dst, E);
    gemm_mma<0><<<dim3(1, MT), 256, SMEM_BYTES>>>(A2, W2 + OFF_MW1, mb1, h1, 128, 320, nullptr);
    ln_silu_split<128><<<(E + 7) / 8, 256>>>(h1, mg, mbn, B2, E);
    gemm_mma<0><<<dim3(1, MT), 256, SMEM_BYTES>>>(B2, W2 + OFF_MW2, mb2, edge, 128, 128, nullptr);
}

// round 9
// speedup vs baseline: 2.2945x; 1.1456x over previous
#include <cuda_runtime.h>
#include <cuda_bf16.h>
#include <cstdint>

#define MAXE 400000
#define MAXN 25000

// ---------------------------------------------------------------------------
// Device scratch. A2/B2 hold hi|lo concatenated bf16 rows (width 2K).
__device__ __nv_bfloat16 g_A2[(size_t)MAXE * 768];
__device__ __nv_bfloat16 g_B2[(size_t)MAXE * 768];
__device__ float g_h1[(size_t)MAXE * 384];
__device__ __nv_bfloat16 g_W2[507904];
__device__ unsigned char g_mask[MAXE];
__device__ int g_last;

// weight pool offsets (bf16 elements), rows are [hi(K) | lo(K)]
#define OFF_IW1 0         // 384 x 768
#define OFF_IW2 294912    // 128 x 768
#define OFF_MW1 393216    // 128 x 640
#define OFF_MW2 475136    // 128 x 256

// ---------------------------------------------------------------------------
static __device__ __forceinline__ uint32_t smem_u32(const void* p) {
    uint32_t a;
    asm("{ .reg .u64 t; cvta.to.shared.u64 t, %1; cvt.u32.u64 %0, t; }" : "=r"(a) : "l"(p));
    return a;
}
static __device__ __forceinline__ void cp_async16(uint32_t s, const void* g) {
    asm volatile("cp.async.cg.shared.global [%0], [%1], 16;" :: "r"(s), "l"(g));
}
static __device__ __forceinline__ void cp_commit() {
    asm volatile("cp.async.commit_group;" ::: "memory");
}
template <int N>
static __device__ __forceinline__ void cp_wait() {
    asm volatile("cp.async.wait_group %0;" :: "n"(N) : "memory");
}
static __device__ __forceinline__ void ldsm4(uint32_t* r, uint32_t a) {
    asm volatile("ldmatrix.sync.aligned.m8n8.x4.shared.b16 {%0,%1,%2,%3}, [%4];"
                 : "=r"(r[0]), "=r"(r[1]), "=r"(r[2]), "=r"(r[3]) : "r"(a));
}
static __device__ __forceinline__ void mma16816(float* d, const uint32_t* a, const uint32_t* b) {
    asm volatile(
        "mma.sync.aligned.m16n8k16.row.col.f32.bf16.bf16.f32 "
        "{%0,%1,%2,%3}, {%4,%5,%6,%7}, {%8,%9}, {%0,%1,%2,%3};"
        : "+f"(d[0]), "+f"(d[1]), "+f"(d[2]), "+f"(d[3])
        : "r"(a[0]), "r"(a[1]), "r"(a[2]), "r"(a[3]), "r"(b[0]), "r"(b[1]));
}

static __device__ __forceinline__ uint32_t pack2(__nv_bfloat16 a, __nv_bfloat16 b) {
    __nv_bfloat162 t = __halves2bfloat162(a, b);
    return *reinterpret_cast<uint32_t*>(&t);
}
static __device__ __forceinline__ void split1(float x, __nv_bfloat16& h, __nv_bfloat16& l) {
    h = __float2bfloat16(x);
    l = __float2bfloat16(x - __bfloat162float(h));
}
static __device__ __forceinline__ void split_store(uint2* oh, uint2* ol, int slot, float4 v) {
    __nv_bfloat16 h0, h1, h2, h3, l0, l1, l2, l3;
    split1(v.x, h0, l0); split1(v.y, h1, l1);
    split1(v.z, h2, l2); split1(v.w, h3, l3);
    uint2 uh, ul;
    uh.x = pack2(h0, h1); uh.y = pack2(h2, h3);
    ul.x = pack2(l0, l1); ul.y = pack2(l2, l3);
    oh[slot] = uh; ol[slot] = ul;
}

// ---------------------------------------------------------------------------
__global__ __launch_bounds__(256) void k_init(float* __restrict__ node, int n)
{
    int i = blockIdx.x * 256 + threadIdx.x;
    if (i == 0) g_last = -1;
    if (i < n) node[i] = 0.f;
}

__global__ __launch_bounds__(256) void k_mask(const int* __restrict__ src,
                                              const int* __restrict__ dst, int E)
{
    int e = blockIdx.x * 256 + threadIdx.x;
    if (e >= E) return;
    bool m = false;
    if (e + 1 < E)
        m = (src[e] == src[e + 1]) && (src[e] != dst[e]) && (src[e + 1] != dst[e + 1]);
    g_mask[e] = m ? 1 : 0;
    if (m) atomicMax(&g_last, e);
}

// split fp32 weight [N,K] -> bf16 [N, 2K] rows [hi | lo]
__global__ __launch_bounds__(256) void k_split(const float* __restrict__ w,
                                               __nv_bfloat16* __restrict__ out,
                                               int Nr, int K)
{
    int i = blockIdx.x * 256 + threadIdx.x;
    if (i >= Nr * K) return;
    int n = i / K, k = i - n * K;
    __nv_bfloat16 h, l;
    split1(w[i], h, l);
    out[(size_t)n * 2 * K + k] = h;
    out[(size_t)n * 2 * K + K + k] = l;
}

// feat -> A2 [E,768]: hi cols 0..319, lo cols 384..703 (angle fills 320..383 / 704..767)
__global__ __launch_bounds__(256) void k_feat(const float* __restrict__ atom,
                                              const float* __restrict__ el,
                                              const int* __restrict__ src,
                                              const int* __restrict__ dst, int E)
{
    int e = (blockIdx.x * 256 + threadIdx.x) >> 5;
    int lane = threadIdx.x & 31;
    if (e >= E) return;
    bool m = (g_mask[e] != 0) && (e != g_last);
    uint2* oh = (uint2*)(g_A2 + (size_t)e * 768);
    uint2* ol = (uint2*)(g_A2 + (size_t)e * 768 + 384);
    if (!m) {
        uint2 z = make_uint2(0u, 0u);
        oh[lane] = z; ol[lane] = z;
        oh[lane + 32] = z; ol[lane + 32] = z;
        if (lane < 16) { oh[lane + 64] = z; ol[lane + 64] = z; }
        return;
    }
    int s = src[e], d = dst[e], d2 = dst[e + 1];
    const float4* p0 = (const float4*)(atom + (size_t)s * 64);
    const float4* p1 = (const float4*)(atom + (size_t)d * 64);
    const float4* p2 = (const float4*)(el + (size_t)e * 64);
    const float4* p3 = (const float4*)(atom + (size_t)d2 * 64);
    const float4* p4 = (const float4*)(el + (size_t)(e + 1) * 64);
    float4 v0 = (lane < 16) ? p0[lane] : p1[lane - 16];
    float4 v1 = (lane < 16) ? p2[lane] : p3[lane - 16];
    split_store(oh, ol, lane, v0);
    split_store(oh, ol, lane + 32, v1);
    if (lane < 16) split_store(oh, ol, lane + 64, p4[lane]);
}

// angle block -> A2 hi cols 320..383, lo cols 704..767
__global__ __launch_bounds__(128) void k_angle(const float* __restrict__ ev,
                                               const float* __restrict__ w1,
                                               const float* __restrict__ b1,
                                               const float* __restrict__ g,
                                               const float* __restrict__ bn,
                                               const float* __restrict__ w2,
                                               const float* __restrict__ b2, int E)
{
    __shared__ float sw2[64 * 64];
    __shared__ float sv[5 * 64];
    for (int i = threadIdx.x; i < 64 * 64; i += 128) sw2[i] = w2[i];
    if (threadIdx.x < 64) {
        int i = threadIdx.x;
        sv[i] = w1[i]; sv[64 + i] = b1[i]; sv[128 + i] = g[i];
        sv[192 + i] = bn[i]; sv[256 + i] = b2[i];
    }
    __syncthreads();
    int e = blockIdx.x * 128 + threadIdx.x;
    if (e >= E) return;
    int last = g_last;
    bool m0 = (g_mask[e] != 0) && (e != last);
    uint2* oh = (uint2*)(g_A2 + (size_t)e * 768 + 320);
    uint2* ol = (uint2*)(g_A2 + (size_t)e * 768 + 704);
    if (!m0) {
        uint2 z = make_uint2(0u, 0u);
        #pragma unroll
        for (int n = 0; n < 16; n++) { oh[n] = z; ol[n] = z; }
        return;
    }
    float c = 0.f;
    if (e + 1 < E && (g_mask[e + 1] != 0) && (e + 1 != last)) {
        float ax = ev[3 * e],       ay = ev[3 * e + 1],       az = ev[3 * e + 2];
        float bx = ev[3 * (e + 1)], by = ev[3 * (e + 1) + 1], bz = ev[3 * (e + 1) + 2];
        float ra = rsqrtf(ax * ax + ay * ay + az * az);
        float rb = rsqrtf(bx * bx + by * by + bz * bz);
        c = (ax * bx + ay * by + az * bz) * ra * rb;
    }
    float x[64];
    float s = 0.f;
    #pragma unroll
    for (int j = 0; j < 64; j++) { x[j] = fmaf(c, sv[j], sv[64 + j]); s += x[j]; }
    float mean = s * (1.f / 64.f);
    float var = 0.f;
    #pragma unroll
    for (int j = 0; j < 64; j++) { float d = x[j] - mean; var = fmaf(d, d, var); }
    var *= (1.f / 64.f);
    float rs = rsqrtf(var + 1e-6f);
    #pragma unroll
    for (int j = 0; j < 64; j++) {
        float t = (x[j] - mean) * rs * sv[128 + j] + sv[192 + j];
        x[j] = t / (1.f + expf(-t));
    }
    float y[64];
    #pragma unroll 4
    for (int n = 0; n < 64; n++) {
        float acc = sv[256 + n];
        const float4* wr = (const float4*)(sw2 + n * 64);
        #pragma unroll
        for (int j4 = 0; j4 < 16; j4++) {
            float4 w4 = wr[j4];
            acc = fmaf(x[4 * j4], w4.x, acc);
            acc = fmaf(x[4 * j4 + 1], w4.y, acc);
            acc = fmaf(x[4 * j4 + 2], w4.z, acc);
            acc = fmaf(x[4 * j4 + 3], w4.w, acc);
        }
        y[n] = acc;
    }
    #pragma unroll
    for (int n = 0; n < 16; n++) {
        float4 v = make_float4(y[4 * n], y[4 * n + 1], y[4 * n + 2], y[4 * n + 3]);
        split_store(oh, ol, n, v);
    }
}

// cat2 -> A2 reused as [E,640]: hi 0..319, lo 320..639
__global__ __launch_bounds__(256) void k_cat2(const float* __restrict__ node,
                                              const float* __restrict__ el,
                                              const int* __restrict__ src,
                                              const int* __restrict__ dst, int E)
{
    int e = (blockIdx.x * 256 + threadIdx.x) >> 5;
    int lane = threadIdx.x & 31;
    if (e >= E) return;
    int s = src[e], d = dst[e];
    uint2* oh = (uint2*)(g_A2 + (size_t)e * 640);
    uint2* ol = (uint2*)(g_A2 + (size_t)e * 640 + 320);
    split_store(oh, ol, lane,      ((const float4*)(node + (size_t)s * 128))[lane]);
    split_store(oh, ol, lane + 32, ((const float4*)(node + (size_t)d * 128))[lane]);
    if (lane < 16)
        split_store(oh, ol, lane + 64, ((const float4*)(el + (size_t)e * 64))[lane]);
}

// LayerNorm + SiLU, fp32 in -> hi|lo bf16 rows of width 2D
template <int D>
__global__ __launch_bounds__(256) void ln_silu_split(const float* __restrict__ X,
                                                     const float* __restrict__ g,
                                                     const float* __restrict__ b,
                                                     __nv_bfloat16* __restrict__ O, int M)
{
    int row = blockIdx.x * 8 + (threadIdx.x >> 5);
    int lane = threadIdx.x & 31;
    if (row >= M) return;
    const float* x = X + (size_t)row * D;
    constexpr int Cc = D / 32;
    float v[Cc];
    float s = 0.f, s2 = 0.f;
    #pragma unroll
    for (int c = 0; c < Cc; c++) {
        v[c] = x[c * 32 + lane];
        s += v[c];
        s2 = fmaf(v[c], v[c], s2);
    }
    #pragma unroll
    for (int o = 16; o; o >>= 1) {
        s += __shfl_xor_sync(0xffffffffu, s, o);
        s2 += __shfl_xor_sync(0xffffffffu, s2, o);
    }
    float mean = s * (1.f / D);
    float var = s2 * (1.f / D) - mean * mean;
    float rs = rsqrtf(var + 1e-6f);
    __nv_bfloat16* hr = O + (size_t)row * 2 * D;
    __nv_bfloat16* lr = hr + D;
    #pragma unroll
    for (int c = 0; c < Cc; c++) {
        float t = (v[c] - mean) * rs * g[c * 32 + lane] + b[c * 32 + lane];
        t = t / (1.f + expf(-t));
        __nv_bfloat16 hh, ll; split1(t, hh, ll);
        hr[c * 32 + lane] = hh;
        lr[c * 32 + lane] = ll;
    }
}

// ---------------------------------------------------------------------------
// bf16x3 mma.sync GEMM, 4-tile staging: per physical k-chunk (BK=64) load
// {Ah, Al, Wh, Wl} once into smem, then run 3 passes (Ah*Wh, Ah*Wl, Al*Wh)
// from the resident stage. A stored [M,2K] rows [Ah|Al]; W stored [N,2K].
// 128x128 block, 256 thr (8 warps 4Mx2N). ATOMIC=1: scatter-add via dstIdx.
#define SM_STRIDE 144              // 64 bf16 + 8 pad = 144 bytes per row
#define SM_TILE   (128 * SM_STRIDE)        // 18432 B
#define SM_STAGE  (4 * SM_TILE)            // Ah, Al, Wh, Wl
#define SMEM_BYTES (2 * SM_STAGE)          // double buffered = 147456 B

template <int ATOMIC>
__global__ __launch_bounds__(256, 1) void gemm_mma(const __nv_bfloat16* __restrict__ A,
                                                   const __nv_bfloat16* __restrict__ W,
                                                   const float* __restrict__ bias,
                                                   float* __restrict__ C, int Nn, int Kseg,
                                                   const int* __restrict__ dstIdx)
{
    extern __shared__ char smem[];
    const uint32_t sb = smem_u32(smem);
    const int tid = threadIdx.x;
    const int lane = tid & 31, wid = tid >> 5;
    const int warp_m = wid & 3, warp_n = wid >> 2;
    const int n0 = blockIdx.x * 128;
    const int m0 = blockIdx.y * 128;
    const int K2 = 2 * Kseg;
    const int NKC = Kseg >> 6;     // physical 64-col k-chunks

    float acc[2][8][4] = {};

    // load one 4-tile stage for k-chunk kc into buffer s
    auto load_stage = [&](int kc, int s) {
        int k0 = kc << 6;
        uint32_t st = sb + s * SM_STAGE;
        #pragma unroll
        for (int i = 0; i < 4; i++) {
            int idx = tid + i * 256;
            int r = idx >> 3, c16 = idx & 7;
            uint32_t so = (uint32_t)(r * SM_STRIDE + c16 * 16);
            const __nv_bfloat16* ar = A + (size_t)(m0 + r) * K2 + k0 + c16 * 8;
            const __nv_bfloat16* wr = W + (size_t)(n0 + r) * K2 + k0 + c16 * 8;
            cp_async16(st + so,               ar);
            cp_async16(st + SM_TILE + so,     ar + Kseg);
            cp_async16(st + 2 * SM_TILE + so, wr);
            cp_async16(st + 3 * SM_TILE + so, wr + Kseg);
        }
        cp_commit();
    };

    // one bf16x3 pass over a resident (A-tile, W-tile) pair
    auto do_pass = [&](uint32_t sa, uint32_t sw) {
        int arow = warp_m * 32 + (lane & 15);
        uint32_t a_ko = (uint32_t)((lane >> 4) * 16);
        int nrow = warp_n * 64 + ((lane >> 4) & 1) * 8 + (lane & 7);
        uint32_t b_ko = (uint32_t)(((lane >> 3) & 1) * 16);
        #pragma unroll
        for (int kk = 0; kk < 4; kk++) {
            uint32_t kb = (uint32_t)(kk * 32);
            uint32_t af[2][4];
            ldsm4(af[0], sa + arow * SM_STRIDE + kb + a_ko);
            ldsm4(af[1], sa + (arow + 16) * SM_STRIDE + kb + a_ko);
            uint32_t bf[8][2];
            #pragma unroll
            for (int in4 = 0; in4 < 4; in4++) {
                uint32_t q[4];
                ldsm4(q, sw + (nrow + in4 * 16) * SM_STRIDE + kb + b_ko);
                bf[in4 * 2][0] = q[0]; bf[in4 * 2][1] = q[1];
                bf[in4 * 2 + 1][0] = q[2]; bf[in4 * 2 + 1][1] = q[3];
            }
            #pragma unroll
            for (int im = 0; im < 2; im++)
                #pragma unroll
                for (int jn = 0; jn < 8; jn++)
                    mma16816(acc[im][jn], af[im], bf[jn]);
        }
    };

    load_stage(0, 0);

    for (int kc = 0; kc < NKC; kc++) {
        if (kc + 1 < NKC) { load_stage(kc + 1, (kc + 1) & 1); cp_wait<1>(); }
        else              { cp_wait<0>(); }
        __syncthreads();
        uint32_t st = sb + (kc & 1) * SM_STAGE;
        do_pass(st,               st + 2 * SM_TILE);  // Ah * Wh
        do_pass(st,               st + 3 * SM_TILE);  // Ah * Wl
        do_pass(st + SM_TILE,     st + 2 * SM_TILE);  // Al * Wh
        __syncthreads();
    }

    // epilogue
    int tq = lane >> 2, tr = lane & 3;
    int rbase = m0 + warp_m * 32 + tq;
    int cb = n0 + warp_n * 64 + tr * 2;
    if (ATOMIC) {
        #pragma unroll
        for (int im = 0; im < 2; im++) {
            int r0 = rbase + im * 16;
            int d0 = dstIdx[r0], d1 = dstIdx[r0 + 8];
            #pragma unroll
            for (int jn = 0; jn < 8; jn++) {
                int col = cb + jn * 8;
                float b0 = bias[col], b1 = bias[col + 1];
                atomicAdd(C + (size_t)d0 * Nn + col,     acc[im][jn][0] + b0);
                atomicAdd(C + (size_t)d0 * Nn + col + 1, acc[im][jn][1] + b1);
                atomicAdd(C + (size_t)d1 * Nn + col,     acc[im][jn][2] + b0);
                atomicAdd(C + (size_t)d1 * Nn + col + 1, acc[im][jn][3] + b1);
            }
        }
    } else {
        #pragma unroll
        for (int im = 0; im < 2; im++) {
            int r0 = rbase + im * 16;
            #pragma unroll
            for (int jn = 0; jn < 8; jn++) {
                int col = cb + jn * 8;
                float b0 = bias[col], b1 = bias[col + 1];
                float2 v0 = make_float2(acc[im][jn][0] + b0, acc[im][jn][1] + b1);
                float2 v1 = make_float2(acc[im][jn][2] + b0, acc[im][jn][3] + b1);
                *(float2*)(C + (size_t)r0 * Nn + col) = v0;
                *(float2*)(C + (size_t)(r0 + 8) * Nn + col) = v1;
            }
        }
    }
}

// ---------------------------------------------------------------------------
extern "C" void kernel_launch(void* const* d_in, const int* in_sizes, int n_in,
                              void* d_out, int out_size)
{
    const float* atom = (const float*)d_in[0];
    const float* el   = (const float*)d_in[1];
    const float* ev   = (const float*)d_in[2];
    const int* eidx   = (const int*)d_in[3];
    const float* aw1 = (const float*)d_in[4];
    const float* ab1 = (const float*)d_in[5];
    const float* ag  = (const float*)d_in[6];
    const float* abn = (const float*)d_in[7];
    const float* aw2 = (const float*)d_in[8];
    const float* ab2 = (const float*)d_in[9];
    const float* iw1 = (const float*)d_in[10];
    const float* ib1 = (const float*)d_in[11];
    const float* ig  = (const float*)d_in[12];
    const float* ibn = (const float*)d_in[13];
    const float* iw2 = (const float*)d_in[14];
    const float* ib2 = (const float*)d_in[15];
    const float* mw1 = (const float*)d_in[16];
    const float* mb1 = (const float*)d_in[17];
    const float* mg  = (const float*)d_in[18];
    const float* mbn = (const float*)d_in[19];
    const float* mw2 = (const float*)d_in[20];
    const float* mb2 = (const float*)d_in[21];

    int Na = in_sizes[0] / 64;   // 25000
    int E  = in_sizes[2] / 3;    // 400000
    const int* src = eidx;
    const int* dst = eidx + E;
    float* node = (float*)d_out;
    float* edge = node + (size_t)Na * 128;

    __nv_bfloat16 *A2, *B2, *W2;
    float* h1;
    cudaGetSymbolAddress((void**)&A2, g_A2);
    cudaGetSymbolAddress((void**)&B2, g_B2);
    cudaGetSymbolAddress((void**)&W2, g_W2);
    cudaGetSymbolAddress((void**)&h1, g_h1);

    cudaFuncSetAttribute(gemm_mma<0>, cudaFuncAttributeMaxDynamicSharedMemorySize, SMEM_BYTES);
    cudaFuncSetAttribute(gemm_mma<1>, cudaFuncAttributeMaxDynamicSharedMemorySize, SMEM_BYTES);

    int MT = E / 128;  // 3125

    // prep
    k_init<<<(Na * 128 + 255) / 256, 256>>>(node, Na * 128);
    k_mask<<<(E + 255) / 256, 256>>>(src, dst, E);
    k_split<<<(384 * 384 + 255) / 256, 256>>>(iw1, W2 + OFF_IW1, 384, 384);
    k_split<<<(128 * 384 + 255) / 256, 256>>>(iw2, W2 + OFF_IW2, 128, 384);
    k_split<<<(128 * 320 + 255) / 256, 256>>>(mw1, W2 + OFF_MW1, 128, 320);
    k_split<<<(128 * 128 + 255) / 256, 256>>>(mw2, W2 + OFF_MW2, 128, 128);

    // inv block
    k_feat<<<(E * 32 + 255) / 256, 256>>>(atom, el, src, dst, E);
    k_angle<<<(E + 127) / 128, 128>>>(ev, aw1, ab1, ag, abn, aw2, ab2, E);
    gemm_mma<0><<<dim3(3, MT), 256, SMEM_BYTES>>>(A2, W2 + OFF_IW1, ib1, h1, 384, 384, nullptr);
    ln_silu_split<384><<<(E + 7) / 8, 256>>>(h1, ig, ibn, B2, E);
    gemm_mma<1><<<dim3(1, MT), 256, SMEM_BYTES>>>(B2, W2 + OFF_IW2, ib2, node, 128, 384, dst);
    // merge block
    k_cat2<<<(E * 32 + 255) / 256, 256>>>(node, el, src, dst, E);
    gemm_mma<0><<<dim3(1, MT), 256, SMEM_BYTES>>>(A2, W2 + OFF_MW1, mb1, h1, 128, 320, nullptr);
    ln_silu_split<128><<<(E + 7) / 8, 256>>>(h1, mg, mbn, B2, E);
    gemm_mma<0><<<dim3(1, MT), 256, SMEM_BYTES>>>(B2, W2 + OFF_MW2, mb2, edge, 128, 128, nullptr);
}